// round 4
// baseline (speedup 1.0000x reference)
#include <cuda_runtime.h>
#include <cuda_bf16.h>

// Leapfrog integrator, GM = 1, A_SCALE = 1. One thread per PARTICLE,
// integrating trail (lane lo) and lead (lane hi) together using packed
// f32x2 math (FFMA2 — Blackwell-only, reachable only via PTX).
// Interior kicks fused (p += dt*a once per interior step); kick coefficient
// folded into the force scalar so kick = p = fma(cf, q, p).

typedef unsigned long long f2;   // packed f32x2 (lo, hi)

__device__ __forceinline__ f2 pack2(float lo, float hi) {
    f2 r; asm("mov.b64 %0, {%1, %2};" : "=l"(r) : "f"(lo), "f"(hi)); return r;
}
__device__ __forceinline__ void unpack2(f2 v, float& lo, float& hi) {
    asm("mov.b64 {%0, %1}, %2;" : "=f"(lo), "=f"(hi) : "l"(v));
}
__device__ __forceinline__ f2 fma2(f2 a, f2 b, f2 c) {
    f2 r; asm("fma.rn.f32x2 %0, %1, %2, %3;" : "=l"(r) : "l"(a), "l"(b), "l"(c)); return r;
}
__device__ __forceinline__ f2 add2(f2 a, f2 b) {
    f2 r; asm("add.rn.f32x2 %0, %1, %2;" : "=l"(r) : "l"(a), "l"(b)); return r;
}
__device__ __forceinline__ f2 mul2(f2 a, f2 b) {
    f2 r; asm("mul.rn.f32x2 %0, %1, %2;" : "=l"(r) : "l"(a), "l"(b)); return r;
}
__device__ __forceinline__ float rsqrt_approx(float x) {
    float y; asm("rsqrt.approx.f32 %0, %1;" : "=f"(y) : "f"(x)); return y;
}
__device__ __forceinline__ float rcp_approx(float x) {
    float y; asm("rcp.approx.f32 %0, %1;" : "=f"(y) : "f"(x)); return y;
}

struct StateP {          // both trajectories, packed per component
    f2 qx, qy, qz, px, py, pz;
};

// cf = c / (r(1+r)^2 + 1e-12) per lane, computed packed except the two
// scalar MUFUs. Uses r + 2r^2 + r^3 = s*(u + 2 + r), s=|q|^2, u=rsqrt(s).
__device__ __forceinline__ f2 kick_coeff2(const StateP& t, f2 cpk,
                                          f2 eps30, f2 two2, f2 eps12) {
    f2 s = fma2(t.qx, t.qx, fma2(t.qy, t.qy, fma2(t.qz, t.qz, eps30)));
    float s0, s1; unpack2(s, s0, s1);
    float u0 = rsqrt_approx(s0);
    float u1 = rsqrt_approx(s1);
    f2 u = pack2(u0, u1);
    f2 r = mul2(s, u);                 // sqrt(s) per lane
    f2 w = add2(add2(u, two2), r);
    f2 den = fma2(s, w, eps12);
    float d0, d1; unpack2(den, d0, d1);
    f2 f = pack2(rcp_approx(d0), rcp_approx(d1));
    return mul2(cpk, f);
}

__device__ __forceinline__ void kick2(StateP& t, f2 cf) {
    t.px = fma2(cf, t.qx, t.px);
    t.py = fma2(cf, t.qy, t.py);
    t.pz = fma2(cf, t.qz, t.pz);
}
__device__ __forceinline__ void drift2(StateP& t, f2 dtp) {
    t.qx = fma2(dtp, t.px, t.qx);
    t.qy = fma2(dtp, t.py, t.qy);
    t.qz = fma2(dtp, t.pz, t.qz);
}

__global__ void __launch_bounds__(64)
stream_integrate_kernel(const float* __restrict__ ts,
                        const float* __restrict__ w_lead,
                        const float* __restrict__ w_trail,
                        const int*   __restrict__ n_steps_p,
                        float* __restrict__ out,
                        int n) {
    int i = blockIdx.x * blockDim.x + threadIdx.x;
    if (i >= n) return;

    // Load both rows: 24*i bytes each, 8B-aligned -> 3x float2.
    const float2* str = reinterpret_cast<const float2*>(w_trail + (size_t)i * 6);
    const float2* sld = reinterpret_cast<const float2*>(w_lead  + (size_t)i * 6);
    float2 t0 = str[0], t1 = str[1], t2 = str[2];
    float2 l0 = sld[0], l1 = sld[1], l2 = sld[2];

    StateP st;
    st.qx = pack2(t0.x, l0.x);
    st.qy = pack2(t0.y, l0.y);
    st.qz = pack2(t1.x, l1.x);
    st.px = pack2(t1.y, l1.y);
    st.py = pack2(t2.x, l2.x);
    st.pz = pack2(t2.y, l2.y);

    float t_f = __ldg(ts + (n - 1)) + 0.001f;
    int   nst = *n_steps_p;
    float dt  = (t_f - ts[i]) / (float)nst;     // one division for both lanes

    f2 dtp   = pack2(dt, dt);
    f2 ndtp  = pack2(-dt, -dt);
    f2 nhdtp = pack2(-0.5f * dt, -0.5f * dt);
    f2 eps30 = pack2(1e-30f, 1e-30f);
    f2 two2  = pack2(2.0f, 2.0f);
    f2 eps12 = pack2(1e-12f, 1e-12f);

    // Opening half kick with accel(q0).
    kick2(st, kick_coeff2(st, nhdtp, eps30, two2, eps12));

    if (nst == 64) {
        #pragma unroll 7
        for (int k = 0; k < 63; ++k) {
            drift2(st, dtp);
            kick2(st, kick_coeff2(st, ndtp, eps30, two2, eps12));
        }
    } else {
        for (int k = 0; k < nst - 1; ++k) {
            drift2(st, dtp);
            kick2(st, kick_coeff2(st, ndtp, eps30, two2, eps12));
        }
    }

    // Closing: drift + half kick.
    drift2(st, dtp);
    kick2(st, kick_coeff2(st, nhdtp, eps30, two2, eps12));

    // Unpack: lane lo = trail -> row 2i, lane hi = lead -> row 2i+1.
    float tqx, lqx, tqy, lqy, tqz, lqz, tpx, lpx, tpy, lpy, tpz, lpz;
    unpack2(st.qx, tqx, lqx); unpack2(st.qy, tqy, lqy); unpack2(st.qz, tqz, lqz);
    unpack2(st.px, tpx, lpx); unpack2(st.py, tpy, lpy); unpack2(st.pz, tpz, lpz);

    float4* dst = reinterpret_cast<float4*>(out + (size_t)i * 12);
    dst[0] = make_float4(tqx, tqy, tqz, tpx);
    dst[1] = make_float4(tpy, tpz, lqx, lqy);
    dst[2] = make_float4(lqz, lpx, lpy, lpz);
}

extern "C" void kernel_launch(void* const* d_in, const int* in_sizes, int n_in,
                              void* d_out, int out_size) {
    const float* ts      = (const float*)d_in[0];
    const float* w_lead  = (const float*)d_in[1];
    const float* w_trail = (const float*)d_in[2];
    const int*   n_steps = (const int*)d_in[3];
    float*       out     = (float*)d_out;

    int n = in_sizes[0];                 // 65536 particles
    int block = 64;                      // 1024 CTAs -> ~7 CTAs/SM, tiny tail
    int grid = (n + block - 1) / block;
    stream_integrate_kernel<<<grid, block>>>(ts, w_lead, w_trail, n_steps, out, n);
}

// round 6
// speedup vs baseline: 1.1830x; 1.1830x over previous
#include <cuda_runtime.h>
#include <cuda_bf16.h>

// Leapfrog integrator, GM = 1, A_SCALE = 1. One thread per (particle, stream):
// tid = 2*i + s (s=0 trail, s=1 lead) == output row index -> contiguous stores.
//
// MUFU-reduction: per interior step only ONE MUFU (rsqrt). The reciprocal
// g = 1/(1+r) is Newton-tracked across steps (seeded by MUFU rcp once):
//   g <- g*(2 - h*g), 3 iterations. Convergent since g_prev*h_new < ~1.25.
// Force scalar: 1/(r(1+r)^2) = u * g^2, u = rsqrt(s), r = s*u.
// Interior kicks fused (one p += dt*a per step); kick coefficient folded:
// kick is p = fma(cf, q, p) with cf = c * u * g^2, c = -dt (or -dt/2).

__device__ __forceinline__ float rsqrt_approx(float x) {
    float y; asm("rsqrt.approx.f32 %0, %1;" : "=f"(y) : "f"(x)); return y;
}
__device__ __forceinline__ float rcp_approx(float x) {
    float y; asm("rcp.approx.f32 %0, %1;" : "=f"(y) : "f"(x)); return y;
}

struct State {
    float qx, qy, qz, px, py, pz;
    float g;                       // tracked 1/(1+r)
};

__device__ __forceinline__ void kick(State& t, float cf) {
    t.px = fmaf(cf, t.qx, t.px);
    t.py = fmaf(cf, t.qy, t.py);
    t.pz = fmaf(cf, t.qz, t.pz);
}
__device__ __forceinline__ void drift(State& t, float dt) {
    t.qx = fmaf(dt, t.px, t.qx);
    t.qy = fmaf(dt, t.py, t.qy);
    t.qz = fmaf(dt, t.pz, t.qz);
}

// One interior/closing force eval + kick with coefficient c (= -dt or -dt/2).
// Single MUFU; refreshes t.g by 3 Newton iterations toward 1/(1+r_new).
__device__ __forceinline__ void force_kick(State& t, float c) {
    float s = fmaf(t.qx, t.qx, fmaf(t.qy, t.qy, fmaf(t.qz, t.qz, 1e-30f)));
    float u = rsqrt_approx(s);          // MUFU (fresh every step)
    float r = s * u;                    // sqrt(s)
    float h = r + 1.0f;
    float g = t.g;                      // ~1/(1+r_prev)
    g = g * fmaf(-h, g, 2.0f);          // Newton 1
    g = g * fmaf(-h, g, 2.0f);          // Newton 2
    g = g * fmaf(-h, g, 2.0f);          // Newton 3
    t.g = g;
    float f = u * (g * g);              // 1/(r(1+r)^2)
    kick(t, c * f);
}

__global__ void __launch_bounds__(64)
stream_integrate_kernel(const float* __restrict__ ts,
                        const float* __restrict__ w_lead,
                        const float* __restrict__ w_trail,
                        const int*   __restrict__ n_steps_p,
                        float* __restrict__ out,
                        int n) {
    int tid = blockIdx.x * blockDim.x + threadIdx.x;
    if (tid >= 2 * n) return;

    int i = tid >> 1;
    int s_ = tid & 1;
    const float* w0 = s_ ? w_lead : w_trail;

    const float2* src = reinterpret_cast<const float2*>(w0 + (size_t)i * 6);
    float2 v0 = src[0];
    float2 v1 = src[1];
    float2 v2 = src[2];

    State st;
    st.qx = v0.x; st.qy = v0.y; st.qz = v1.x;
    st.px = v1.y; st.py = v2.x; st.pz = v2.y;

    float t_f = __ldg(ts + (n - 1)) + 0.001f;
    int   nst = *n_steps_p;
    float dt  = (t_f - ts[i]) / (float)nst;
    float ndt  = -dt;
    float nhdt = 0.5f * ndt;

    // Opening half kick: seed g with a real MUFU rcp, full force eval.
    {
        float s = fmaf(st.qx, st.qx, fmaf(st.qy, st.qy, fmaf(st.qz, st.qz, 1e-30f)));
        float u = rsqrt_approx(s);
        float r = s * u;
        float h = r + 1.0f;
        float g = rcp_approx(h);
        g = g * fmaf(-h, g, 2.0f);      // one Newton to ~1ulp seed
        st.g = g;
        float f = u * (g * g);
        kick(st, nhdt * f);
    }

    if (nst == 64) {
        #pragma unroll 7
        for (int k = 0; k < 63; ++k) {
            drift(st, dt);
            force_kick(st, ndt);
        }
    } else {
        for (int k = 0; k < nst - 1; ++k) {
            drift(st, dt);
            force_kick(st, ndt);
        }
    }

    // Closing step: drift + half kick.
    drift(st, dt);
    force_kick(st, nhdt);

    float2* dst = reinterpret_cast<float2*>(out + (size_t)tid * 6);
    dst[0] = make_float2(st.qx, st.qy);
    dst[1] = make_float2(st.qz, st.px);
    dst[2] = make_float2(st.py, st.pz);
}

extern "C" void kernel_launch(void* const* d_in, const int* in_sizes, int n_in,
                              void* d_out, int out_size) {
    const float* ts      = (const float*)d_in[0];
    const float* w_lead  = (const float*)d_in[1];
    const float* w_trail = (const float*)d_in[2];
    const int*   n_steps = (const int*)d_in[3];
    float*       out     = (float*)d_out;

    int n = in_sizes[0];                 // 65536 particles
    int total = 2 * n;                   // 131072 trajectories
    int block = 64;                      // 4096 CTAs -> 28v27/SM, ~3.6% tail
    int grid = (total + block - 1) / block;
    stream_integrate_kernel<<<grid, block>>>(ts, w_lead, w_trail, n_steps, out, n);
}